// round 15
// baseline (speedup 1.0000x reference)
#include <cuda_runtime.h>
#include <cuda_fp16.h>
#include <cstdint>
#include <cstddef>

#define N_TOK 4096
#define DCH   256
#define NHEAD 4
#define DHEAD 64
#define KSPLIT 2

__device__ __half   g_xT  [N_TOK * DCH];           // [tok][ch] f16
__device__ __half   g_Wqh [DCH * DCH];
__device__ __half   g_Wkh [DCH * DCH];
__device__ __half   g_Wvh [DCH * DCH];
__device__ __half   g_W1h [(DCH/2) * DCH];
__device__ __half   g_W2h [(DCH/2) * (DCH/2)];
__device__ __half   g_W3h [DCH * (DCH/2)];
__device__ uint8_t  g_Q8  [NHEAD * N_TOK * DHEAD]; // [h][tok][d] e4m3
__device__ uint8_t  g_K8  [NHEAD * N_TOK * DHEAD]; // [h][tok][d] e4m3
__device__ __half   g_Vh  [DCH * N_TOK];           // [ch][tok] f16
__device__ float    g_pO  [KSPLIT * DCH * N_TOK];
__device__ float    g_pden[KSPLIT * NHEAD * N_TOK];
__device__ __half   g_msgT[N_TOK * DCH];
__device__ __half   g_h1T [N_TOK * (DCH/2)];
__device__ __half   g_h2T [N_TOK * (DCH/2)];

__device__ __forceinline__ float ex2f(float x) {
    float r; asm("ex2.approx.f32 %0, %1;" : "=f"(r) : "f"(x)); return r;
}
__device__ __forceinline__ void hmma(float* c, const uint32_t* a, const uint32_t* b) {
    asm volatile(
        "mma.sync.aligned.m16n8k16.row.col.f32.f16.f16.f32 "
        "{%0,%1,%2,%3}, {%4,%5,%6,%7}, {%8,%9}, {%0,%1,%2,%3};"
        : "+f"(c[0]), "+f"(c[1]), "+f"(c[2]), "+f"(c[3])
        : "r"(a[0]), "r"(a[1]), "r"(a[2]), "r"(a[3]), "r"(b[0]), "r"(b[1]));
}
// fp8 e4m3 MMA, K=32 per step (2x MACs per instruction vs f16 k16)
__device__ __forceinline__ void qmma(float* c, const uint32_t* a, const uint32_t* b) {
    asm volatile(
        "mma.sync.aligned.m16n8k32.row.col.f32.e4m3.e4m3.f32 "
        "{%0,%1,%2,%3}, {%4,%5,%6,%7}, {%8,%9}, {%0,%1,%2,%3};"
        : "+f"(c[0]), "+f"(c[1]), "+f"(c[2]), "+f"(c[3])
        : "r"(a[0]), "r"(a[1]), "r"(a[2]), "r"(a[3]), "r"(b[0]), "r"(b[1]));
}
// pack two f32 -> e4m3x2 (16-bit; first operand = upper byte = value at d+1)
__device__ __forceinline__ unsigned short f2e4m3x2(float hi, float lo) {
    unsigned short r;
    asm("cvt.rn.satfinite.e4m3x2.f32 %0, %1, %2;" : "=h"(r) : "f"(hi), "f"(lo));
    return r;
}

// ---------------- weight f32 -> f16 ----------------
__global__ void __launch_bounds__(256)
wconv_kernel(const float* __restrict__ wq, const float* __restrict__ wk,
             const float* __restrict__ wv, const float* __restrict__ w1,
             const float* __restrict__ w2, const float* __restrict__ w3)
{
    const int i = blockIdx.x * 256 + threadIdx.x;
    if (i < DCH * DCH) {
        g_Wqh[i] = __float2half(wq[i]);
        g_Wkh[i] = __float2half(wk[i]);
        g_Wvh[i] = __float2half(wv[i]);
    }
    if (i < (DCH/2) * DCH) {
        g_W1h[i] = __float2half(w1[i]);
        g_W3h[i] = __float2half(w3[i]);
    }
    if (i < (DCH/2) * (DCH/2)) g_W2h[i] = __float2half(w2[i]);
}

// ---------------- x [ch][tok] f32 -> xT [tok][ch] f16 ----------------
__global__ void __launch_bounds__(256)
xconv_kernel(const float* __restrict__ x)
{
    __shared__ float tile[64 * 65];
    const int tid = threadIdx.x;
    const int tok0 = blockIdx.x * 64, ch0 = blockIdx.y * 64;
    const int ch = tid >> 2;
    #pragma unroll
    for (int it = 0; it < 4; it++) {
        const int col = (tid & 3) * 16 + it * 4;
        const float4 v = *(const float4*)(x + (size_t)(ch0 + ch) * N_TOK + tok0 + col);
        tile[(col+0)*65 + ch] = v.x; tile[(col+1)*65 + ch] = v.y;
        tile[(col+2)*65 + ch] = v.z; tile[(col+3)*65 + ch] = v.w;
    }
    __syncthreads();
    #pragma unroll
    for (int it = 0; it < 2; it++) {
        const int u = it * 256 + tid;
        const int tok = u >> 3, c8 = (u & 7) * 8;
        __half hh[8];
        #pragma unroll
        for (int j = 0; j < 8; j++) hh[j] = __float2half(tile[tok*65 + c8 + j]);
        *(uint4*)(g_xT + (size_t)(tok0 + tok) * DCH + ch0 + c8) = *(uint4*)hh;
    }
}

// ---------------- split-K combine -> msgT [tok][ch] f16 ----------------
__global__ void __launch_bounds__(256)
combine_kernel()
{
    __shared__ float tile[64 * 65];
    const int tid = threadIdx.x;
    const int tok0 = blockIdx.x * 64, h = blockIdx.y, ch0 = h * 64;
    const int ch = tid >> 2;
    #pragma unroll
    for (int it = 0; it < 4; it++) {
        const int col = (tid & 3) * 16 + it * 4;
        const size_t ro = (size_t)(ch0 + ch) * N_TOK + tok0 + col;
        const float4 a  = *(const float4*)(g_pO + ro);
        const float4 b  = *(const float4*)(g_pO + (size_t)DCH * N_TOK + ro);
        const size_t doff = (size_t)h * N_TOK + tok0 + col;
        const float4 d0 = *(const float4*)(g_pden + doff);
        const float4 d1 = *(const float4*)(g_pden + (size_t)NHEAD * N_TOK + doff);
        tile[(col+0)*65 + ch] = (a.x + b.x) / (d0.x + d1.x);
        tile[(col+1)*65 + ch] = (a.y + b.y) / (d0.y + d1.y);
        tile[(col+2)*65 + ch] = (a.z + b.z) / (d0.z + d1.z);
        tile[(col+3)*65 + ch] = (a.w + b.w) / (d0.w + d1.w);
    }
    __syncthreads();
    #pragma unroll
    for (int it = 0; it < 2; it++) {
        const int u = it * 256 + tid;
        const int tok = u >> 3, c8 = (u & 7) * 8;
        __half hh[8];
        #pragma unroll
        for (int j = 0; j < 8; j++) hh[j] = __float2half(tile[tok*65 + c8 + j]);
        *(uint4*)(g_msgT + (size_t)(tok0 + tok) * DCH + ch0 + c8) = *(uint4*)hh;
    }
}

// ---------------------------------------------------------------------------
// HMMA GEMM template (MLP + output; unchanged from R11 passing kernel).
// ---------------------------------------------------------------------------
template<int KD, int EPI>
__global__ void __launch_bounds__(128, 3)
hgemm_kernel(const __half* __restrict__ A, const __half* __restrict__ W,
             const float* __restrict__ bias,
             const float* __restrict__ gamma, const float* __restrict__ beta,
             const float* __restrict__ resid, void* __restrict__ dst)
{
    __shared__ __align__(16) float smf[64 * 129];
    uint32_t* AF = (uint32_t*)smf;
    const int tid = threadIdx.x;
    const int lane = tid & 31, wid = tid >> 5;
    const int wm = wid & 1, wn = wid >> 1;
    const int g = lane >> 2, tq = lane & 3;
    const int tok0 = blockIdx.x * 64, ch_blk = blockIdx.y * 128;
    constexpr int KC8 = KD / 8;
    constexpr int SH  = (KD == 256) ? 5 : 4;
    constexpr int RW  = KD / 2;

    #pragma unroll
    for (int it = 0; it < (64 * KC8) / 128; it++) {
        const int u = it * 128 + tid;
        const int c8 = u & (KC8 - 1), tok = u >> SH;
        const uint4 v = *(const uint4*)(A + (size_t)(tok0 + tok) * KD + c8 * 8);
        *(uint4*)(AF + tok * RW + (c8 ^ (tok & 7)) * 4) = v;
    }
    __syncthreads();

    float c[2][8][4];
    #pragma unroll
    for (int i = 0; i < 2; i++)
        #pragma unroll
        for (int j = 0; j < 8; j++)
            #pragma unroll
            for (int q = 0; q < 4; q++) c[i][j][q] = 0.0f;

    const __half* Wp = W + (size_t)(ch_blk + wn * 64) * KD;

    #pragma unroll 2
    for (int kc = 0; kc < KD / 16; kc++) {
        uint32_t a[2][4];
        #pragma unroll
        for (int mt = 0; mt < 2; mt++) {
            const int row = wm * 32 + mt * 16 + g;
            const int lo = ((kc * 2    ) ^ g) * 4 + tq;
            const int hi = ((kc * 2 + 1) ^ g) * 4 + tq;
            a[mt][0] = AF[(row    ) * RW + lo];
            a[mt][1] = AF[(row + 8) * RW + lo];
            a[mt][2] = AF[(row    ) * RW + hi];
            a[mt][3] = AF[(row + 8) * RW + hi];
        }
        #pragma unroll
        for (int nt = 0; nt < 8; nt++) {
            const __half* wrow = Wp + (size_t)(nt * 8 + g) * KD + kc * 16 + tq * 2;
            uint32_t b[2];
            b[0] = *(const uint32_t*)(wrow);
            b[1] = *(const uint32_t*)(wrow + 8);
            hmma(c[0][nt], a[0], b);
            hmma(c[1][nt], a[1], b);
        }
    }

    if (EPI == 1) {
        __half* o = (__half*)dst;
        const int M = gridDim.y * 128;
        const float RSQ = rsqrtf(1.0f + 1e-5f);
        #pragma unroll
        for (int mt = 0; mt < 2; mt++) {
            const int tok = tok0 + wm * 32 + mt * 16 + g;
            #pragma unroll
            for (int nt = 0; nt < 8; nt++) {
                const int ch = ch_blk + wn * 64 + nt * 8 + tq * 2;
                const float s0 = gamma[ch] * RSQ, s1 = gamma[ch + 1] * RSQ;
                const float e0 = beta[ch],        e1 = beta[ch + 1];
                const float b0 = bias[ch],        b1 = bias[ch + 1];
                const float v0 = fmaxf((c[mt][nt][0] + b0) * s0 + e0, 0.0f);
                const float v1 = fmaxf((c[mt][nt][1] + b1) * s1 + e1, 0.0f);
                const float v2 = fmaxf((c[mt][nt][2] + b0) * s0 + e0, 0.0f);
                const float v3 = fmaxf((c[mt][nt][3] + b1) * s1 + e1, 0.0f);
                __half* p = o + (size_t)tok * M + ch;
                *(__half2*)p           = __floats2half2_rn(v0, v1);
                *(__half2*)(p + 8 * M) = __floats2half2_rn(v2, v3);
            }
        }
    } else {
        __syncthreads();
        #pragma unroll
        for (int mt = 0; mt < 2; mt++) {
            const int tl = wm * 32 + mt * 16 + g;
            #pragma unroll
            for (int nt = 0; nt < 8; nt++) {
                const int cl = wn * 64 + nt * 8 + tq * 2;
                const float b0 = bias[ch_blk + cl], b1 = bias[ch_blk + cl + 1];
                smf[(tl    ) * 129 + cl    ] = c[mt][nt][0] + b0;
                smf[(tl    ) * 129 + cl + 1] = c[mt][nt][1] + b1;
                smf[(tl + 8) * 129 + cl    ] = c[mt][nt][2] + b0;
                smf[(tl + 8) * 129 + cl + 1] = c[mt][nt][3] + b1;
            }
        }
        __syncthreads();
        float* o = (float*)dst;
        #pragma unroll
        for (int it = 0; it < 16; it++) {
            const int u = it * 128 + tid;
            const int ch = u >> 4, t4 = (u & 15) * 4;
            const float4 r = *(const float4*)(resid + (size_t)(ch_blk + ch) * N_TOK + tok0 + t4);
            float4 v;
            v.x = smf[(t4+0)*129 + ch] + r.x;
            v.y = smf[(t4+1)*129 + ch] + r.y;
            v.z = smf[(t4+2)*129 + ch] + r.z;
            v.w = smf[(t4+3)*129 + ch] + r.w;
            *(float4*)(o + (size_t)(ch_blk + ch) * N_TOK + tok0 + t4) = v;
        }
    }
}

// ---------------------------------------------------------------------------
// Fused QKV GEMM. Q/K epilogue now writes e4m3 [h][tok][d]; V f16 [ch][tok].
// ---------------------------------------------------------------------------
__global__ void __launch_bounds__(128, 3)
hgemm_qkv(const __half* __restrict__ A,
          const __half* __restrict__ Wq, const __half* __restrict__ Wk,
          const __half* __restrict__ Wv,
          const float* __restrict__ bq, const float* __restrict__ bk,
          const float* __restrict__ bv)
{
    constexpr int KD = 256, KC8 = 32, SH = 5, RW = 128;
    __shared__ __align__(16) float smf[64 * 129];
    uint32_t* AF = (uint32_t*)smf;
    const int tid = threadIdx.x;
    const int lane = tid & 31, wid = tid >> 5;
    const int wm = wid & 1, wn = wid >> 1;
    const int g = lane >> 2, tq = lane & 3;
    const int tok0 = blockIdx.x * 64;
    const int s = blockIdx.y, which = s >> 1, ch_blk = (s & 1) * 128;
    const __half* W = (which == 0) ? Wq : (which == 1) ? Wk : Wv;
    const float* bias = (which == 0) ? bq : (which == 1) ? bk : bv;

    #pragma unroll
    for (int it = 0; it < (64 * KC8) / 128; it++) {
        const int u = it * 128 + tid;
        const int c8 = u & (KC8 - 1), tok = u >> SH;
        const uint4 v = *(const uint4*)(A + (size_t)(tok0 + tok) * KD + c8 * 8);
        *(uint4*)(AF + tok * RW + (c8 ^ (tok & 7)) * 4) = v;
    }
    __syncthreads();

    float c[2][8][4];
    #pragma unroll
    for (int i = 0; i < 2; i++)
        #pragma unroll
        for (int j = 0; j < 8; j++)
            #pragma unroll
            for (int q = 0; q < 4; q++) c[i][j][q] = 0.0f;

    const __half* Wp = W + (size_t)(ch_blk + wn * 64) * KD;

    #pragma unroll 2
    for (int kc = 0; kc < KD / 16; kc++) {
        uint32_t a[2][4];
        #pragma unroll
        for (int mt = 0; mt < 2; mt++) {
            const int row = wm * 32 + mt * 16 + g;
            const int lo = ((kc * 2    ) ^ g) * 4 + tq;
            const int hi = ((kc * 2 + 1) ^ g) * 4 + tq;
            a[mt][0] = AF[(row    ) * RW + lo];
            a[mt][1] = AF[(row + 8) * RW + lo];
            a[mt][2] = AF[(row    ) * RW + hi];
            a[mt][3] = AF[(row + 8) * RW + hi];
        }
        #pragma unroll
        for (int nt = 0; nt < 8; nt++) {
            const __half* wrow = Wp + (size_t)(nt * 8 + g) * KD + kc * 16 + tq * 2;
            uint32_t b[2];
            b[0] = *(const uint32_t*)(wrow);
            b[1] = *(const uint32_t*)(wrow + 8);
            hmma(c[0][nt], a[0], b);
            hmma(c[1][nt], a[1], b);
        }
    }

    if (which < 2) {
        uint8_t* q8 = (which == 0) ? g_Q8 : g_K8;
        #pragma unroll
        for (int mt = 0; mt < 2; mt++) {
            const int tok = tok0 + wm * 32 + mt * 16 + g;
            #pragma unroll
            for (int nt = 0; nt < 8; nt++) {
                const int ch = ch_blk + wn * 64 + nt * 8 + tq * 2;
                const int hh = ch >> 6, d = ch & 63;
                const float b0 = bias[ch], b1 = bias[ch + 1];
                uint8_t* p = q8 + ((size_t)hh * N_TOK + tok) * DHEAD + d;
                *(unsigned short*)p               = f2e4m3x2(c[mt][nt][1] + b1, c[mt][nt][0] + b0);
                *(unsigned short*)(p + 8 * DHEAD) = f2e4m3x2(c[mt][nt][3] + b1, c[mt][nt][2] + b0);
            }
        }
    } else {
        __syncthreads();
        #pragma unroll
        for (int mt = 0; mt < 2; mt++) {
            const int tl = wm * 32 + mt * 16 + g;
            #pragma unroll
            for (int nt = 0; nt < 8; nt++) {
                const int cl = wn * 64 + nt * 8 + tq * 2;
                const float b0 = bias[ch_blk + cl], b1 = bias[ch_blk + cl + 1];
                smf[(tl    ) * 129 + cl    ] = c[mt][nt][0] + b0;
                smf[(tl    ) * 129 + cl + 1] = c[mt][nt][1] + b1;
                smf[(tl + 8) * 129 + cl    ] = c[mt][nt][2] + b0;
                smf[(tl + 8) * 129 + cl + 1] = c[mt][nt][3] + b1;
            }
        }
        __syncthreads();
        #pragma unroll
        for (int it = 0; it < 8; it++) {
            const int u = it * 128 + tid;
            const int ch = u >> 3, t8 = (u & 7) * 8;
            __half hh[8];
            #pragma unroll
            for (int j = 0; j < 8; j++) hh[j] = __float2half(smf[(t8 + j) * 129 + ch]);
            *(uint4*)(g_Vh + (size_t)(ch_blk + ch) * N_TOK + tok0 + t8) = *(uint4*)hh;
        }
    }
}

// ---------------------------------------------------------------------------
// Flash attention. QK in fp8 e4m3 (m16n8k32, 2 kc-steps -> QK hmmas halved),
// PV in f16 (S-fragment -> P A-fragment register identity preserved).
// R11 shape: 256 thr, warp-m=32, grid (4 heads, 16 qtiles, 2 ksplit).
// KF: fp8 B-frags [kc(2)][nt(16)][lane(32)][reg(2)] u32 + kc*2 skew (8.2KB).
// VF: f16 B-frags unchanged.
// ---------------------------------------------------------------------------
__global__ void __launch_bounds__(256, 1)
attn_kernel(const float* __restrict__ spat)
{
    __shared__ __align__(16) char smbuf[33792];
    uint32_t* KF = (uint32_t*)smbuf;            // fp8 K frags, <=8208B
    uint32_t* VF = (uint32_t*)(smbuf + 8448);   // f16 V frags, 16436B
    float*    SO = (float*)smbuf;               // out transpose [128][66]

    const int tid  = threadIdx.x;
    const int w    = tid >> 5;
    const int lane = tid & 31;
    const int h    = blockIdx.x;
    const int q0   = blockIdx.y * 256;
    const int kt   = blockIdx.z;
    const int g    = lane >> 2;
    const int tq   = lane & 3;
    const float SCL = 0.1803368801111204f;   // log2(e)/8

    // ---- persistent fp8 Q A-frags: [mt][kc][4] ----
    uint32_t aq[2][2][4];
    #pragma unroll
    for (int mt = 0; mt < 2; mt++) {
        const uint8_t* qp = g_Q8 + ((size_t)h * N_TOK + q0 + w * 32 + mt * 16) * DHEAD;
        #pragma unroll
        for (int kc = 0; kc < 2; kc++) {
            const int d0 = kc * 32 + tq * 4;
            aq[mt][kc][0] = *(const uint32_t*)(qp + (size_t)(g    ) * DHEAD + d0);
            aq[mt][kc][1] = *(const uint32_t*)(qp + (size_t)(g + 8) * DHEAD + d0);
            aq[mt][kc][2] = *(const uint32_t*)(qp + (size_t)(g    ) * DHEAD + d0 + 16);
            aq[mt][kc][3] = *(const uint32_t*)(qp + (size_t)(g + 8) * DHEAD + d0 + 16);
        }
    }

    float oacc[2][8][4];
    #pragma unroll
    for (int m = 0; m < 2; m++)
        #pragma unroll
        for (int i = 0; i < 8; i++)
            #pragma unroll
            for (int j = 0; j < 4; j++) oacc[m][i][j] = 0.0f;
    float den[2][2] = {{0.0f, 0.0f}, {0.0f, 0.0f}};

    const float* sp[2][2];
    #pragma unroll
    for (int mt = 0; mt < 2; mt++) {
        sp[mt][0] = spat + (size_t)(q0 + w * 32 + mt * 16 + g    ) * N_TOK + tq * 2;
        sp[mt][1] = spat + (size_t)(q0 + w * 32 + mt * 16 + g + 8) * N_TOK + tq * 2;
    }

    #pragma unroll 1
    for (int t = 0; t < 32 / KSPLIT; t++) {
        const int kb = (kt * (32 / KSPLIT) + t) * 128;
        __syncthreads();

        // ---- stage K fp8 frags: 128 rows x 64B = 512 uint4, 2 iters ----
        // chunk (tok, c16): bytes d = c16*16..+15 -> kc=c16>>1, r=c16&1,
        // u32 #m holds tq=m. addr = (kc*16+nt)*64 + kc*2 + g*8 + m*2 + r.
        #pragma unroll
        for (int it = 0; it < 2; it++) {
            const int u = it * 256 + tid;
            const int tok = u >> 2, c16 = u & 3;
            const uint4 v = *(const uint4*)(g_K8 + ((size_t)h * N_TOK + kb + tok) * DHEAD + c16 * 16);
            const int kc = c16 >> 1, r = c16 & 1;
            uint32_t* p = KF + ((kc * 16 + (tok >> 3)) * 64) + kc * 2 + (tok & 7) * 8 + r;
            p[0] = v.x; p[2] = v.y; p[4] = v.z; p[6] = v.w;
        }
        // ---- stage V f16 frags (unchanged layout) ----
        #pragma unroll
        for (int it = 0; it < 4; it++) {
            const int d  = tid >> 2;
            const int c8 = it * 4 + (tid & 3);
            const uint4 v = *(const uint4*)(g_Vh + ((size_t)(h * DHEAD + d)) * N_TOK + kb + c8 * 8);
            const int kc = c8 >> 1, r = c8 & 1, nt = d >> 3;
            uint32_t* p = VF + (kc * 8 + nt) * 64 + kc * 2 + (d & 7) * 8 + r;
            p[0] = v.x; p[2] = v.y; p[4] = v.z; p[6] = v.w;
        }
        __syncthreads();

        // ---- 8 chunks of 16 keys: fp8 QK -> exp -> f16 PV ----
        #pragma unroll
        for (int c = 0; c < 8; c++) {
            float cS[2][2][4];
            #pragma unroll
            for (int m = 0; m < 2; m++)
                #pragma unroll
                for (int j = 0; j < 2; j++)
                    #pragma unroll
                    for (int q = 0; q < 4; q++) cS[m][j][q] = 0.0f;
            #pragma unroll
            for (int kc = 0; kc < 2; kc++) {
                const uint32_t* b0 = KF + (kc * 16 + 2 * c    ) * 64 + kc * 2 + lane * 2;
                const uint32_t* b1 = KF + (kc * 16 + 2 * c + 1) * 64 + kc * 2 + lane * 2;
                qmma(cS[0][0], aq[0][kc], b0);
                qmma(cS[1][0], aq[1][kc], b0);
                qmma(cS[0][1], aq[0][kc], b1);
                qmma(cS[1][1], aq[1][kc], b1);
            }
            uint32_t aP[2][4];
            #pragma unroll
            for (int mt = 0; mt < 2; mt++)
                #pragma unroll
                for (int j = 0; j < 2; j++) {
                    const int nt = 2 * c + j;
                    const float2 slo = *(const float2*)(sp[mt][0] + kb + nt * 8);
                    const float2 shi = *(const float2*)(sp[mt][1] + kb + nt * 8);
                    const float p0 = ex2f(cS[mt][j][0] * slo.x * SCL);
                    const float p1 = ex2f(cS[mt][j][1] * slo.y * SCL);
                    const float p2 = ex2f(cS[mt][j][2] * shi.x * SCL);
                    const float p3 = ex2f(cS[mt][j][3] * shi.y * SCL);
                    den[mt][0] += p0 + p1;
                    den[mt][1] += p2 + p3;
                    __half2 h01 = __floats2half2_rn(p0, p1);
                    __half2 h23 = __floats2half2_rn(p2, p3);
                    aP[mt][j * 2 + 0] = *(uint32_t*)&h01;
                    aP[mt][j * 2 + 1] = *(uint32_t*)&h23;
                }
            #pragma unroll
            for (int ntv = 0; ntv < 8; ntv++) {
                const uint32_t* vb = VF + (c * 8 + ntv) * 64 + c * 2 + lane * 2;
                hmma(oacc[0][ntv], aP[0], vb);
                hmma(oacc[1][ntv], aP[1], vb);
            }
        }
    }

    #pragma unroll
    for (int mt = 0; mt < 2; mt++) {
        den[mt][0] += __shfl_xor_sync(0xFFFFFFFFu, den[mt][0], 1);
        den[mt][0] += __shfl_xor_sync(0xFFFFFFFFu, den[mt][0], 2);
        den[mt][1] += __shfl_xor_sync(0xFFFFFFFFu, den[mt][1], 1);
        den[mt][1] += __shfl_xor_sync(0xFFFFFFFFu, den[mt][1], 2);
    }
    if (tq == 0) {
        float* dp = g_pden + (size_t)kt * NHEAD * N_TOK + (size_t)h * N_TOK + q0 + w * 32;
        dp[g]          = den[0][0];
        dp[g + 8]      = den[0][1];
        dp[16 + g]     = den[1][0];
        dp[16 + g + 8] = den[1][1];
    }

    float* pO = g_pO + (size_t)kt * DCH * N_TOK;
    #pragma unroll
    for (int rep = 0; rep < 2; rep++) {
        __syncthreads();
        if ((w >> 2) == rep) {
            const int wl = w & 3;
            #pragma unroll
            for (int mt = 0; mt < 2; mt++) {
                const int rowL = wl * 32 + mt * 16 + g, rowH = rowL + 8;
                #pragma unroll
                for (int nt = 0; nt < 8; nt++) {
                    const int col = nt * 8 + tq * 2;
                    *(float2*)(SO + rowL * 66 + col) = make_float2(oacc[mt][nt][0], oacc[mt][nt][1]);
                    *(float2*)(SO + rowH * 66 + col) = make_float2(oacc[mt][nt][2], oacc[mt][nt][3]);
                }
            }
        }
        __syncthreads();
        const int qb = q0 + rep * 128;
        #pragma unroll
        for (int it = 0; it < 8; it++) {
            const int u = it * 256 + tid;
            const int qc = u & 31, d = u >> 5;
            float4 o;
            o.x = SO[(qc * 4 + 0) * 66 + d];
            o.y = SO[(qc * 4 + 1) * 66 + d];
            o.z = SO[(qc * 4 + 2) * 66 + d];
            o.w = SO[(qc * 4 + 3) * 66 + d];
            *(float4*)(pO + (size_t)(h * DHEAD + d) * N_TOK + qb + qc * 4) = o;
        }
    }
}

// ---------------------------------------------------------------------------
extern "C" void kernel_launch(void* const* d_in, const int* in_sizes, int n_in,
                              void* d_out, int out_size)
{
    const float* x    = (const float*)d_in[0];
    const float* spat = (const float*)d_in[1];
    const float* Wq   = (const float*)d_in[2];
    const float* bq   = (const float*)d_in[3];
    const float* Wk   = (const float*)d_in[4];
    const float* bk   = (const float*)d_in[5];
    const float* Wv   = (const float*)d_in[6];
    const float* bv   = (const float*)d_in[7];
    const float* W1   = (const float*)d_in[8];
    const float* b1   = (const float*)d_in[9];
    const float* g1   = (const float*)d_in[10];
    const float* be1  = (const float*)d_in[11];
    const float* W2   = (const float*)d_in[12];
    const float* b2   = (const float*)d_in[13];
    const float* g2   = (const float*)d_in[14];
    const float* be2  = (const float*)d_in[15];
    const float* W3   = (const float*)d_in[16];
    const float* b3   = (const float*)d_in[17];
    float* out = (float*)d_out;

    void *pxT, *pWq, *pWk, *pWv, *pW1, *pW2, *pW3, *pMT, *pH1, *pH2;
    cudaGetSymbolAddress(&pxT, g_xT);
    cudaGetSymbolAddress(&pWq, g_Wqh);
    cudaGetSymbolAddress(&pWk, g_Wkh);
    cudaGetSymbolAddress(&pWv, g_Wvh);
    cudaGetSymbolAddress(&pW1, g_W1h);
    cudaGetSymbolAddress(&pW2, g_W2h);
    cudaGetSymbolAddress(&pW3, g_W3h);
    cudaGetSymbolAddress(&pMT, g_msgT);
    cudaGetSymbolAddress(&pH1, g_h1T);
    cudaGetSymbolAddress(&pH2, g_h2T);

    wconv_kernel<<<256, 256>>>(Wq, Wk, Wv, W1, W2, W3);
    xconv_kernel<<<dim3(64, 4), 256>>>(x);
    hgemm_qkv<<<dim3(64, 6), 128>>>((const __half*)pxT,
        (const __half*)pWq, (const __half*)pWk, (const __half*)pWv, bq, bk, bv);
    attn_kernel<<<dim3(4, 16, KSPLIT), 256>>>(spat);
    combine_kernel<<<dim3(64, 4), 256>>>();
    hgemm_kernel<256, 1><<<dim3(64, 1), 128>>>((const __half*)pMT, (const __half*)pW1, b1, g1, be1, nullptr, pH1);
    hgemm_kernel<128, 1><<<dim3(64, 1), 128>>>((const __half*)pH1, (const __half*)pW2, b2, g2, be2, nullptr, pH2);
    hgemm_kernel<128, 2><<<dim3(64, 2), 128>>>((const __half*)pH2, (const __half*)pW3, b3, nullptr, nullptr, x, out);
}

// round 16
// speedup vs baseline: 1.0121x; 1.0121x over previous
#include <cuda_runtime.h>
#include <cuda_fp16.h>
#include <cstdint>
#include <cstddef>

#define N_TOK 4096
#define DCH   256
#define NHEAD 4
#define DHEAD 64
#define KSPLIT 2

__device__ __half   g_xT  [N_TOK * DCH];           // [tok][ch] f16
__device__ __half   g_Wqh [DCH * DCH];
__device__ __half   g_Wkh [DCH * DCH];
__device__ __half   g_Wvh [DCH * DCH];
__device__ __half   g_W1h [(DCH/2) * DCH];
__device__ __half   g_W2h [(DCH/2) * (DCH/2)];
__device__ __half   g_W3h [DCH * (DCH/2)];
__device__ uint8_t  g_Q8  [NHEAD * N_TOK * DHEAD]; // [h][tok][d] e4m3
__device__ uint8_t  g_K8  [NHEAD * N_TOK * DHEAD]; // [h][tok][d] e4m3
__device__ __half   g_Vh  [DCH * N_TOK];           // [ch][tok] f16
__device__ float    g_pO  [KSPLIT * DCH * N_TOK];
__device__ float    g_pden[KSPLIT * NHEAD * N_TOK];
__device__ __half   g_msgT[N_TOK * DCH];
__device__ __half   g_h1T [N_TOK * (DCH/2)];
__device__ __half   g_h2T [N_TOK * (DCH/2)];

__device__ __forceinline__ float ex2f(float x) {
    float r; asm("ex2.approx.f32 %0, %1;" : "=f"(r) : "f"(x)); return r;
}
__device__ __forceinline__ void hmma(float* c, const uint32_t* a, const uint32_t* b) {
    asm volatile(
        "mma.sync.aligned.m16n8k16.row.col.f32.f16.f16.f32 "
        "{%0,%1,%2,%3}, {%4,%5,%6,%7}, {%8,%9}, {%0,%1,%2,%3};"
        : "+f"(c[0]), "+f"(c[1]), "+f"(c[2]), "+f"(c[3])
        : "r"(a[0]), "r"(a[1]), "r"(a[2]), "r"(a[3]), "r"(b[0]), "r"(b[1]));
}
// fp8 e4m3 MMA, K=32 per step (2x MACs per instruction vs f16 k16)
__device__ __forceinline__ void qmma(float* c, const uint32_t* a, const uint32_t* b) {
    asm volatile(
        "mma.sync.aligned.m16n8k32.row.col.f32.e4m3.e4m3.f32 "
        "{%0,%1,%2,%3}, {%4,%5,%6,%7}, {%8,%9}, {%0,%1,%2,%3};"
        : "+f"(c[0]), "+f"(c[1]), "+f"(c[2]), "+f"(c[3])
        : "r"(a[0]), "r"(a[1]), "r"(a[2]), "r"(a[3]), "r"(b[0]), "r"(b[1]));
}
// pack two f32 -> e4m3x2 (16-bit; first operand = upper byte = value at d+1)
__device__ __forceinline__ unsigned short f2e4m3x2(float hi, float lo) {
    unsigned short r;
    asm("cvt.rn.satfinite.e4m3x2.f32 %0, %1, %2;" : "=h"(r) : "f"(hi), "f"(lo));
    return r;
}

// ---------------- weight f32 -> f16 ----------------
__global__ void __launch_bounds__(256)
wconv_kernel(const float* __restrict__ wq, const float* __restrict__ wk,
             const float* __restrict__ wv, const float* __restrict__ w1,
             const float* __restrict__ w2, const float* __restrict__ w3)
{
    const int i = blockIdx.x * 256 + threadIdx.x;
    if (i < DCH * DCH) {
        g_Wqh[i] = __float2half(wq[i]);
        g_Wkh[i] = __float2half(wk[i]);
        g_Wvh[i] = __float2half(wv[i]);
    }
    if (i < (DCH/2) * DCH) {
        g_W1h[i] = __float2half(w1[i]);
        g_W3h[i] = __float2half(w3[i]);
    }
    if (i < (DCH/2) * (DCH/2)) g_W2h[i] = __float2half(w2[i]);
}

// ---------------- x [ch][tok] f32 -> xT [tok][ch] f16 ----------------
__global__ void __launch_bounds__(256)
xconv_kernel(const float* __restrict__ x)
{
    __shared__ float tile[64 * 65];
    const int tid = threadIdx.x;
    const int tok0 = blockIdx.x * 64, ch0 = blockIdx.y * 64;
    const int ch = tid >> 2;
    #pragma unroll
    for (int it = 0; it < 4; it++) {
        const int col = (tid & 3) * 16 + it * 4;
        const float4 v = *(const float4*)(x + (size_t)(ch0 + ch) * N_TOK + tok0 + col);
        tile[(col+0)*65 + ch] = v.x; tile[(col+1)*65 + ch] = v.y;
        tile[(col+2)*65 + ch] = v.z; tile[(col+3)*65 + ch] = v.w;
    }
    __syncthreads();
    #pragma unroll
    for (int it = 0; it < 2; it++) {
        const int u = it * 256 + tid;
        const int tok = u >> 3, c8 = (u & 7) * 8;
        __half hh[8];
        #pragma unroll
        for (int j = 0; j < 8; j++) hh[j] = __float2half(tile[tok*65 + c8 + j]);
        *(uint4*)(g_xT + (size_t)(tok0 + tok) * DCH + ch0 + c8) = *(uint4*)hh;
    }
}

// ---------------- split-K combine -> msgT [tok][ch] f16 ----------------
__global__ void __launch_bounds__(256)
combine_kernel()
{
    __shared__ float tile[64 * 65];
    const int tid = threadIdx.x;
    const int tok0 = blockIdx.x * 64, h = blockIdx.y, ch0 = h * 64;
    const int ch = tid >> 2;
    #pragma unroll
    for (int it = 0; it < 4; it++) {
        const int col = (tid & 3) * 16 + it * 4;
        const size_t ro = (size_t)(ch0 + ch) * N_TOK + tok0 + col;
        const float4 a  = *(const float4*)(g_pO + ro);
        const float4 b  = *(const float4*)(g_pO + (size_t)DCH * N_TOK + ro);
        const size_t doff = (size_t)h * N_TOK + tok0 + col;
        const float4 d0 = *(const float4*)(g_pden + doff);
        const float4 d1 = *(const float4*)(g_pden + (size_t)NHEAD * N_TOK + doff);
        tile[(col+0)*65 + ch] = (a.x + b.x) / (d0.x + d1.x);
        tile[(col+1)*65 + ch] = (a.y + b.y) / (d0.y + d1.y);
        tile[(col+2)*65 + ch] = (a.z + b.z) / (d0.z + d1.z);
        tile[(col+3)*65 + ch] = (a.w + b.w) / (d0.w + d1.w);
    }
    __syncthreads();
    #pragma unroll
    for (int it = 0; it < 2; it++) {
        const int u = it * 256 + tid;
        const int tok = u >> 3, c8 = (u & 7) * 8;
        __half hh[8];
        #pragma unroll
        for (int j = 0; j < 8; j++) hh[j] = __float2half(tile[tok*65 + c8 + j]);
        *(uint4*)(g_msgT + (size_t)(tok0 + tok) * DCH + ch0 + c8) = *(uint4*)hh;
    }
}

// ---------------------------------------------------------------------------
// HMMA GEMM template (MLP + output; unchanged from R11 passing kernel).
// ---------------------------------------------------------------------------
template<int KD, int EPI>
__global__ void __launch_bounds__(128, 3)
hgemm_kernel(const __half* __restrict__ A, const __half* __restrict__ W,
             const float* __restrict__ bias,
             const float* __restrict__ gamma, const float* __restrict__ beta,
             const float* __restrict__ resid, void* __restrict__ dst)
{
    __shared__ __align__(16) float smf[64 * 129];
    uint32_t* AF = (uint32_t*)smf;
    const int tid = threadIdx.x;
    const int lane = tid & 31, wid = tid >> 5;
    const int wm = wid & 1, wn = wid >> 1;
    const int g = lane >> 2, tq = lane & 3;
    const int tok0 = blockIdx.x * 64, ch_blk = blockIdx.y * 128;
    constexpr int KC8 = KD / 8;
    constexpr int SH  = (KD == 256) ? 5 : 4;
    constexpr int RW  = KD / 2;

    #pragma unroll
    for (int it = 0; it < (64 * KC8) / 128; it++) {
        const int u = it * 128 + tid;
        const int c8 = u & (KC8 - 1), tok = u >> SH;
        const uint4 v = *(const uint4*)(A + (size_t)(tok0 + tok) * KD + c8 * 8);
        *(uint4*)(AF + tok * RW + (c8 ^ (tok & 7)) * 4) = v;
    }
    __syncthreads();

    float c[2][8][4];
    #pragma unroll
    for (int i = 0; i < 2; i++)
        #pragma unroll
        for (int j = 0; j < 8; j++)
            #pragma unroll
            for (int q = 0; q < 4; q++) c[i][j][q] = 0.0f;

    const __half* Wp = W + (size_t)(ch_blk + wn * 64) * KD;

    #pragma unroll 2
    for (int kc = 0; kc < KD / 16; kc++) {
        uint32_t a[2][4];
        #pragma unroll
        for (int mt = 0; mt < 2; mt++) {
            const int row = wm * 32 + mt * 16 + g;
            const int lo = ((kc * 2    ) ^ g) * 4 + tq;
            const int hi = ((kc * 2 + 1) ^ g) * 4 + tq;
            a[mt][0] = AF[(row    ) * RW + lo];
            a[mt][1] = AF[(row + 8) * RW + lo];
            a[mt][2] = AF[(row    ) * RW + hi];
            a[mt][3] = AF[(row + 8) * RW + hi];
        }
        #pragma unroll
        for (int nt = 0; nt < 8; nt++) {
            const __half* wrow = Wp + (size_t)(nt * 8 + g) * KD + kc * 16 + tq * 2;
            uint32_t b[2];
            b[0] = *(const uint32_t*)(wrow);
            b[1] = *(const uint32_t*)(wrow + 8);
            hmma(c[0][nt], a[0], b);
            hmma(c[1][nt], a[1], b);
        }
    }

    if (EPI == 1) {
        __half* o = (__half*)dst;
        const int M = gridDim.y * 128;
        const float RSQ = rsqrtf(1.0f + 1e-5f);
        #pragma unroll
        for (int mt = 0; mt < 2; mt++) {
            const int tok = tok0 + wm * 32 + mt * 16 + g;
            #pragma unroll
            for (int nt = 0; nt < 8; nt++) {
                const int ch = ch_blk + wn * 64 + nt * 8 + tq * 2;
                const float s0 = gamma[ch] * RSQ, s1 = gamma[ch + 1] * RSQ;
                const float e0 = beta[ch],        e1 = beta[ch + 1];
                const float b0 = bias[ch],        b1 = bias[ch + 1];
                const float v0 = fmaxf((c[mt][nt][0] + b0) * s0 + e0, 0.0f);
                const float v1 = fmaxf((c[mt][nt][1] + b1) * s1 + e1, 0.0f);
                const float v2 = fmaxf((c[mt][nt][2] + b0) * s0 + e0, 0.0f);
                const float v3 = fmaxf((c[mt][nt][3] + b1) * s1 + e1, 0.0f);
                __half* p = o + (size_t)tok * M + ch;
                *(__half2*)p           = __floats2half2_rn(v0, v1);
                *(__half2*)(p + 8 * M) = __floats2half2_rn(v2, v3);
            }
        }
    } else {
        __syncthreads();
        #pragma unroll
        for (int mt = 0; mt < 2; mt++) {
            const int tl = wm * 32 + mt * 16 + g;
            #pragma unroll
            for (int nt = 0; nt < 8; nt++) {
                const int cl = wn * 64 + nt * 8 + tq * 2;
                const float b0 = bias[ch_blk + cl], b1 = bias[ch_blk + cl + 1];
                smf[(tl    ) * 129 + cl    ] = c[mt][nt][0] + b0;
                smf[(tl    ) * 129 + cl + 1] = c[mt][nt][1] + b1;
                smf[(tl + 8) * 129 + cl    ] = c[mt][nt][2] + b0;
                smf[(tl + 8) * 129 + cl + 1] = c[mt][nt][3] + b1;
            }
        }
        __syncthreads();
        float* o = (float*)dst;
        #pragma unroll
        for (int it = 0; it < 16; it++) {
            const int u = it * 128 + tid;
            const int ch = u >> 4, t4 = (u & 15) * 4;
            const float4 r = *(const float4*)(resid + (size_t)(ch_blk + ch) * N_TOK + tok0 + t4);
            float4 v;
            v.x = smf[(t4+0)*129 + ch] + r.x;
            v.y = smf[(t4+1)*129 + ch] + r.y;
            v.z = smf[(t4+2)*129 + ch] + r.z;
            v.w = smf[(t4+3)*129 + ch] + r.w;
            *(float4*)(o + (size_t)(ch_blk + ch) * N_TOK + tok0 + t4) = v;
        }
    }
}

// ---------------------------------------------------------------------------
// Fused QKV GEMM. Q/K epilogue now writes e4m3 [h][tok][d]; V f16 [ch][tok].
// ---------------------------------------------------------------------------
__global__ void __launch_bounds__(128, 3)
hgemm_qkv(const __half* __restrict__ A,
          const __half* __restrict__ Wq, const __half* __restrict__ Wk,
          const __half* __restrict__ Wv,
          const float* __restrict__ bq, const float* __restrict__ bk,
          const float* __restrict__ bv)
{
    constexpr int KD = 256, KC8 = 32, SH = 5, RW = 128;
    __shared__ __align__(16) float smf[64 * 129];
    uint32_t* AF = (uint32_t*)smf;
    const int tid = threadIdx.x;
    const int lane = tid & 31, wid = tid >> 5;
    const int wm = wid & 1, wn = wid >> 1;
    const int g = lane >> 2, tq = lane & 3;
    const int tok0 = blockIdx.x * 64;
    const int s = blockIdx.y, which = s >> 1, ch_blk = (s & 1) * 128;
    const __half* W = (which == 0) ? Wq : (which == 1) ? Wk : Wv;
    const float* bias = (which == 0) ? bq : (which == 1) ? bk : bv;

    #pragma unroll
    for (int it = 0; it < (64 * KC8) / 128; it++) {
        const int u = it * 128 + tid;
        const int c8 = u & (KC8 - 1), tok = u >> SH;
        const uint4 v = *(const uint4*)(A + (size_t)(tok0 + tok) * KD + c8 * 8);
        *(uint4*)(AF + tok * RW + (c8 ^ (tok & 7)) * 4) = v;
    }
    __syncthreads();

    float c[2][8][4];
    #pragma unroll
    for (int i = 0; i < 2; i++)
        #pragma unroll
        for (int j = 0; j < 8; j++)
            #pragma unroll
            for (int q = 0; q < 4; q++) c[i][j][q] = 0.0f;

    const __half* Wp = W + (size_t)(ch_blk + wn * 64) * KD;

    #pragma unroll 2
    for (int kc = 0; kc < KD / 16; kc++) {
        uint32_t a[2][4];
        #pragma unroll
        for (int mt = 0; mt < 2; mt++) {
            const int row = wm * 32 + mt * 16 + g;
            const int lo = ((kc * 2    ) ^ g) * 4 + tq;
            const int hi = ((kc * 2 + 1) ^ g) * 4 + tq;
            a[mt][0] = AF[(row    ) * RW + lo];
            a[mt][1] = AF[(row + 8) * RW + lo];
            a[mt][2] = AF[(row    ) * RW + hi];
            a[mt][3] = AF[(row + 8) * RW + hi];
        }
        #pragma unroll
        for (int nt = 0; nt < 8; nt++) {
            const __half* wrow = Wp + (size_t)(nt * 8 + g) * KD + kc * 16 + tq * 2;
            uint32_t b[2];
            b[0] = *(const uint32_t*)(wrow);
            b[1] = *(const uint32_t*)(wrow + 8);
            hmma(c[0][nt], a[0], b);
            hmma(c[1][nt], a[1], b);
        }
    }

    if (which < 2) {
        uint8_t* q8 = (which == 0) ? g_Q8 : g_K8;
        #pragma unroll
        for (int mt = 0; mt < 2; mt++) {
            const int tok = tok0 + wm * 32 + mt * 16 + g;
            #pragma unroll
            for (int nt = 0; nt < 8; nt++) {
                const int ch = ch_blk + wn * 64 + nt * 8 + tq * 2;
                const int hh = ch >> 6, d = ch & 63;
                const float b0 = bias[ch], b1 = bias[ch + 1];
                uint8_t* p = q8 + ((size_t)hh * N_TOK + tok) * DHEAD + d;
                *(unsigned short*)p               = f2e4m3x2(c[mt][nt][1] + b1, c[mt][nt][0] + b0);
                *(unsigned short*)(p + 8 * DHEAD) = f2e4m3x2(c[mt][nt][3] + b1, c[mt][nt][2] + b0);
            }
        }
    } else {
        __syncthreads();
        #pragma unroll
        for (int mt = 0; mt < 2; mt++) {
            const int tl = wm * 32 + mt * 16 + g;
            #pragma unroll
            for (int nt = 0; nt < 8; nt++) {
                const int cl = wn * 64 + nt * 8 + tq * 2;
                const float b0 = bias[ch_blk + cl], b1 = bias[ch_blk + cl + 1];
                smf[(tl    ) * 129 + cl    ] = c[mt][nt][0] + b0;
                smf[(tl    ) * 129 + cl + 1] = c[mt][nt][1] + b1;
                smf[(tl + 8) * 129 + cl    ] = c[mt][nt][2] + b0;
                smf[(tl + 8) * 129 + cl + 1] = c[mt][nt][3] + b1;
            }
        }
        __syncthreads();
        #pragma unroll
        for (int it = 0; it < 8; it++) {
            const int u = it * 128 + tid;
            const int ch = u >> 3, t8 = (u & 7) * 8;
            __half hh[8];
            #pragma unroll
            for (int j = 0; j < 8; j++) hh[j] = __float2half(smf[(t8 + j) * 129 + ch]);
            *(uint4*)(g_Vh + (size_t)(ch_blk + ch) * N_TOK + tok0 + t8) = *(uint4*)hh;
        }
    }
}

// ---------------------------------------------------------------------------
// Flash attention. QK in fp8 e4m3 (m16n8k32, 2 kc-steps -> QK hmmas halved),
// PV in f16 (S-fragment -> P A-fragment register identity preserved).
// R11 shape: 256 thr, warp-m=32, grid (4 heads, 16 qtiles, 2 ksplit).
// KF: fp8 B-frags [kc(2)][nt(16)][lane(32)][reg(2)] u32 + kc*2 skew (8.2KB).
// VF: f16 B-frags unchanged.
// ---------------------------------------------------------------------------
__global__ void __launch_bounds__(256, 1)
attn_kernel(const float* __restrict__ spat)
{
    __shared__ __align__(16) char smbuf[33792];
    uint32_t* KF = (uint32_t*)smbuf;            // fp8 K frags, <=8208B
    uint32_t* VF = (uint32_t*)(smbuf + 8448);   // f16 V frags, 16436B
    float*    SO = (float*)smbuf;               // out transpose [128][66]

    const int tid  = threadIdx.x;
    const int w    = tid >> 5;
    const int lane = tid & 31;
    const int h    = blockIdx.x;
    const int q0   = blockIdx.y * 256;
    const int kt   = blockIdx.z;
    const int g    = lane >> 2;
    const int tq   = lane & 3;
    const float SCL = 0.1803368801111204f;   // log2(e)/8

    // ---- persistent fp8 Q A-frags: [mt][kc][4] ----
    uint32_t aq[2][2][4];
    #pragma unroll
    for (int mt = 0; mt < 2; mt++) {
        const uint8_t* qp = g_Q8 + ((size_t)h * N_TOK + q0 + w * 32 + mt * 16) * DHEAD;
        #pragma unroll
        for (int kc = 0; kc < 2; kc++) {
            const int d0 = kc * 32 + tq * 4;
            aq[mt][kc][0] = *(const uint32_t*)(qp + (size_t)(g    ) * DHEAD + d0);
            aq[mt][kc][1] = *(const uint32_t*)(qp + (size_t)(g + 8) * DHEAD + d0);
            aq[mt][kc][2] = *(const uint32_t*)(qp + (size_t)(g    ) * DHEAD + d0 + 16);
            aq[mt][kc][3] = *(const uint32_t*)(qp + (size_t)(g + 8) * DHEAD + d0 + 16);
        }
    }

    float oacc[2][8][4];
    #pragma unroll
    for (int m = 0; m < 2; m++)
        #pragma unroll
        for (int i = 0; i < 8; i++)
            #pragma unroll
            for (int j = 0; j < 4; j++) oacc[m][i][j] = 0.0f;
    float den[2][2] = {{0.0f, 0.0f}, {0.0f, 0.0f}};

    const float* sp[2][2];
    #pragma unroll
    for (int mt = 0; mt < 2; mt++) {
        sp[mt][0] = spat + (size_t)(q0 + w * 32 + mt * 16 + g    ) * N_TOK + tq * 2;
        sp[mt][1] = spat + (size_t)(q0 + w * 32 + mt * 16 + g + 8) * N_TOK + tq * 2;
    }

    #pragma unroll 1
    for (int t = 0; t < 32 / KSPLIT; t++) {
        const int kb = (kt * (32 / KSPLIT) + t) * 128;
        __syncthreads();

        // ---- stage K fp8 frags: 128 rows x 64B = 512 uint4, 2 iters ----
        // chunk (tok, c16): bytes d = c16*16..+15 -> kc=c16>>1, r=c16&1,
        // u32 #m holds tq=m. addr = (kc*16+nt)*64 + kc*2 + g*8 + m*2 + r.
        #pragma unroll
        for (int it = 0; it < 2; it++) {
            const int u = it * 256 + tid;
            const int tok = u >> 2, c16 = u & 3;
            const uint4 v = *(const uint4*)(g_K8 + ((size_t)h * N_TOK + kb + tok) * DHEAD + c16 * 16);
            const int kc = c16 >> 1, r = c16 & 1;
            uint32_t* p = KF + ((kc * 16 + (tok >> 3)) * 64) + kc * 2 + (tok & 7) * 8 + r;
            p[0] = v.x; p[2] = v.y; p[4] = v.z; p[6] = v.w;
        }
        // ---- stage V f16 frags (unchanged layout) ----
        #pragma unroll
        for (int it = 0; it < 4; it++) {
            const int d  = tid >> 2;
            const int c8 = it * 4 + (tid & 3);
            const uint4 v = *(const uint4*)(g_Vh + ((size_t)(h * DHEAD + d)) * N_TOK + kb + c8 * 8);
            const int kc = c8 >> 1, r = c8 & 1, nt = d >> 3;
            uint32_t* p = VF + (kc * 8 + nt) * 64 + kc * 2 + (d & 7) * 8 + r;
            p[0] = v.x; p[2] = v.y; p[4] = v.z; p[6] = v.w;
        }
        __syncthreads();

        // ---- 8 chunks of 16 keys: fp8 QK -> exp -> f16 PV ----
        #pragma unroll
        for (int c = 0; c < 8; c++) {
            float cS[2][2][4];
            #pragma unroll
            for (int m = 0; m < 2; m++)
                #pragma unroll
                for (int j = 0; j < 2; j++)
                    #pragma unroll
                    for (int q = 0; q < 4; q++) cS[m][j][q] = 0.0f;
            #pragma unroll
            for (int kc = 0; kc < 2; kc++) {
                const uint32_t* b0 = KF + (kc * 16 + 2 * c    ) * 64 + kc * 2 + lane * 2;
                const uint32_t* b1 = KF + (kc * 16 + 2 * c + 1) * 64 + kc * 2 + lane * 2;
                qmma(cS[0][0], aq[0][kc], b0);
                qmma(cS[1][0], aq[1][kc], b0);
                qmma(cS[0][1], aq[0][kc], b1);
                qmma(cS[1][1], aq[1][kc], b1);
            }
            uint32_t aP[2][4];
            #pragma unroll
            for (int mt = 0; mt < 2; mt++)
                #pragma unroll
                for (int j = 0; j < 2; j++) {
                    const int nt = 2 * c + j;
                    const float2 slo = *(const float2*)(sp[mt][0] + kb + nt * 8);
                    const float2 shi = *(const float2*)(sp[mt][1] + kb + nt * 8);
                    const float p0 = ex2f(cS[mt][j][0] * slo.x * SCL);
                    const float p1 = ex2f(cS[mt][j][1] * slo.y * SCL);
                    const float p2 = ex2f(cS[mt][j][2] * shi.x * SCL);
                    const float p3 = ex2f(cS[mt][j][3] * shi.y * SCL);
                    den[mt][0] += p0 + p1;
                    den[mt][1] += p2 + p3;
                    __half2 h01 = __floats2half2_rn(p0, p1);
                    __half2 h23 = __floats2half2_rn(p2, p3);
                    aP[mt][j * 2 + 0] = *(uint32_t*)&h01;
                    aP[mt][j * 2 + 1] = *(uint32_t*)&h23;
                }
            #pragma unroll
            for (int ntv = 0; ntv < 8; ntv++) {
                const uint32_t* vb = VF + (c * 8 + ntv) * 64 + c * 2 + lane * 2;
                hmma(oacc[0][ntv], aP[0], vb);
                hmma(oacc[1][ntv], aP[1], vb);
            }
        }
    }

    #pragma unroll
    for (int mt = 0; mt < 2; mt++) {
        den[mt][0] += __shfl_xor_sync(0xFFFFFFFFu, den[mt][0], 1);
        den[mt][0] += __shfl_xor_sync(0xFFFFFFFFu, den[mt][0], 2);
        den[mt][1] += __shfl_xor_sync(0xFFFFFFFFu, den[mt][1], 1);
        den[mt][1] += __shfl_xor_sync(0xFFFFFFFFu, den[mt][1], 2);
    }
    if (tq == 0) {
        float* dp = g_pden + (size_t)kt * NHEAD * N_TOK + (size_t)h * N_TOK + q0 + w * 32;
        dp[g]          = den[0][0];
        dp[g + 8]      = den[0][1];
        dp[16 + g]     = den[1][0];
        dp[16 + g + 8] = den[1][1];
    }

    float* pO = g_pO + (size_t)kt * DCH * N_TOK;
    #pragma unroll
    for (int rep = 0; rep < 2; rep++) {
        __syncthreads();
        if ((w >> 2) == rep) {
            const int wl = w & 3;
            #pragma unroll
            for (int mt = 0; mt < 2; mt++) {
                const int rowL = wl * 32 + mt * 16 + g, rowH = rowL + 8;
                #pragma unroll
                for (int nt = 0; nt < 8; nt++) {
                    const int col = nt * 8 + tq * 2;
                    *(float2*)(SO + rowL * 66 + col) = make_float2(oacc[mt][nt][0], oacc[mt][nt][1]);
                    *(float2*)(SO + rowH * 66 + col) = make_float2(oacc[mt][nt][2], oacc[mt][nt][3]);
                }
            }
        }
        __syncthreads();
        const int qb = q0 + rep * 128;
        #pragma unroll
        for (int it = 0; it < 8; it++) {
            const int u = it * 256 + tid;
            const int qc = u & 31, d = u >> 5;
            float4 o;
            o.x = SO[(qc * 4 + 0) * 66 + d];
            o.y = SO[(qc * 4 + 1) * 66 + d];
            o.z = SO[(qc * 4 + 2) * 66 + d];
            o.w = SO[(qc * 4 + 3) * 66 + d];
            *(float4*)(pO + (size_t)(h * DHEAD + d) * N_TOK + qb + qc * 4) = o;
        }
    }
}

// ---------------------------------------------------------------------------
extern "C" void kernel_launch(void* const* d_in, const int* in_sizes, int n_in,
                              void* d_out, int out_size)
{
    const float* x    = (const float*)d_in[0];
    const float* spat = (const float*)d_in[1];
    const float* Wq   = (const float*)d_in[2];
    const float* bq   = (const float*)d_in[3];
    const float* Wk   = (const float*)d_in[4];
    const float* bk   = (const float*)d_in[5];
    const float* Wv   = (const float*)d_in[6];
    const float* bv   = (const float*)d_in[7];
    const float* W1   = (const float*)d_in[8];
    const float* b1   = (const float*)d_in[9];
    const float* g1   = (const float*)d_in[10];
    const float* be1  = (const float*)d_in[11];
    const float* W2   = (const float*)d_in[12];
    const float* b2   = (const float*)d_in[13];
    const float* g2   = (const float*)d_in[14];
    const float* be2  = (const float*)d_in[15];
    const float* W3   = (const float*)d_in[16];
    const float* b3   = (const float*)d_in[17];
    float* out = (float*)d_out;

    void *pxT, *pWq, *pWk, *pWv, *pW1, *pW2, *pW3, *pMT, *pH1, *pH2;
    cudaGetSymbolAddress(&pxT, g_xT);
    cudaGetSymbolAddress(&pWq, g_Wqh);
    cudaGetSymbolAddress(&pWk, g_Wkh);
    cudaGetSymbolAddress(&pWv, g_Wvh);
    cudaGetSymbolAddress(&pW1, g_W1h);
    cudaGetSymbolAddress(&pW2, g_W2h);
    cudaGetSymbolAddress(&pW3, g_W3h);
    cudaGetSymbolAddress(&pMT, g_msgT);
    cudaGetSymbolAddress(&pH1, g_h1T);
    cudaGetSymbolAddress(&pH2, g_h2T);

    wconv_kernel<<<256, 256>>>(Wq, Wk, Wv, W1, W2, W3);
    xconv_kernel<<<dim3(64, 4), 256>>>(x);
    hgemm_qkv<<<dim3(64, 6), 128>>>((const __half*)pxT,
        (const __half*)pWq, (const __half*)pWk, (const __half*)pWv, bq, bk, bv);
    attn_kernel<<<dim3(4, 16, KSPLIT), 256>>>(spat);
    combine_kernel<<<dim3(64, 4), 256>>>();
    hgemm_kernel<256, 1><<<dim3(64, 1), 128>>>((const __half*)pMT, (const __half*)pW1, b1, g1, be1, nullptr, pH1);
    hgemm_kernel<128, 1><<<dim3(64, 1), 128>>>((const __half*)pH1, (const __half*)pW2, b2, g2, be2, nullptr, pH2);
    hgemm_kernel<128, 2><<<dim3(64, 2), 128>>>((const __half*)pH2, (const __half*)pW3, b3, nullptr, nullptr, x, out);
}